// round 1
// baseline (speedup 1.0000x reference)
#include <cuda_runtime.h>

#define NB    2
#define N1V   4096
#define N2V   16384
#define CINV  512
#define CSKV  256
#define COUTV 256

// Scratch (no allocations allowed): h1 transposed [b][n1][co], knn idx/weights.
__device__ float g_h1T[(size_t)NB * N1V * COUTV];
__device__ int   g_idx[NB * N2V * 3];
__device__ float g_wgt[NB * N2V * 3];

// ---------------------------------------------------------------------------
// Kernel 1: h1T[b][n][co] = relu( bn( W1 @ x1 ) )   (stored n-major, co-contig)
// Tiles: 128(co) x 128(n) x 16(k), 256 threads, 8x8 microtile.
// ---------------------------------------------------------------------------
__global__ __launch_bounds__(256)
void conv1_kernel(const float* __restrict__ W1, const float* __restrict__ x1,
                  const float* __restrict__ g1, const float* __restrict__ b1,
                  const float* __restrict__ m1, const float* __restrict__ v1)
{
    __shared__ float As[16][136];   // [k][co], padded for bank-conflict-free access
    __shared__ float Bs[16][128];   // [k][n]
    __shared__ float sc_s[128], sh_s[128];

    const int t  = threadIdx.x;
    const int tx = t & 15, ty = t >> 4;
    const int n0  = blockIdx.x * 128;
    const int co0 = blockIdx.y * 128;
    const int bb  = blockIdx.z;

    if (t < 128) {
        int co = co0 + t;
        float sc = g1[co] * rsqrtf(v1[co] + 1e-5f);
        sc_s[t] = sc;
        sh_s[t] = b1[co] - m1[co] * sc;
    }

    const float* xb = x1 + (size_t)bb * CINV * N1V;

    float acc[8][8];
    #pragma unroll
    for (int i = 0; i < 8; i++)
        #pragma unroll
        for (int j = 0; j < 8; j++) acc[i][j] = 0.f;

    const int arow = t & 63;         // co within 64-half
    const int akk  = (t >> 6) * 4;   // k quad start
    const int brow = t >> 5;         // 0..7
    const int bcol = (t & 31) * 4;

    for (int k0 = 0; k0 < CINV; k0 += 16) {
        __syncthreads();
        #pragma unroll
        for (int r = 0; r < 2; r++) {
            int co_r = arow + r * 64;
            float4 w = *(const float4*)&W1[(size_t)(co0 + co_r) * CINV + k0 + akk];
            As[akk + 0][co_r] = w.x;
            As[akk + 1][co_r] = w.y;
            As[akk + 2][co_r] = w.z;
            As[akk + 3][co_r] = w.w;
        }
        #pragma unroll
        for (int r = 0; r < 2; r++) {
            int kk = r * 8 + brow;
            *(float4*)&Bs[kk][bcol] =
                *(const float4*)&xb[(size_t)(k0 + kk) * N1V + n0 + bcol];
        }
        __syncthreads();
        #pragma unroll
        for (int kk = 0; kk < 16; kk++) {
            float4 a0 = *(const float4*)&As[kk][ty * 4];
            float4 a1 = *(const float4*)&As[kk][64 + ty * 4];
            float4 c0 = *(const float4*)&Bs[kk][tx * 4];
            float4 c1 = *(const float4*)&Bs[kk][64 + tx * 4];
            float av[8] = {a0.x, a0.y, a0.z, a0.w, a1.x, a1.y, a1.z, a1.w};
            float bv[8] = {c0.x, c0.y, c0.z, c0.w, c1.x, c1.y, c1.z, c1.w};
            #pragma unroll
            for (int i = 0; i < 8; i++)
                #pragma unroll
                for (int j = 0; j < 8; j++)
                    acc[i][j] = fmaf(av[i], bv[j], acc[i][j]);
        }
    }
    __syncthreads();

    float sc[8], sh[8];
    #pragma unroll
    for (int i = 0; i < 8; i++) {
        int ci = (i < 4) ? (ty * 4 + i) : (64 + ty * 4 + (i - 4));
        sc[i] = sc_s[ci];
        sh[i] = sh_s[ci];
    }

    #pragma unroll
    for (int j = 0; j < 8; j++) {
        int n = n0 + ((j < 4) ? (tx * 4 + j) : (64 + tx * 4 + (j - 4)));
        float* dst = &g_h1T[((size_t)bb * N1V + n) * COUTV + co0];
        float4 v0, v1q;
        v0.x  = fmaxf(fmaf(acc[0][j], sc[0], sh[0]), 0.f);
        v0.y  = fmaxf(fmaf(acc[1][j], sc[1], sh[1]), 0.f);
        v0.z  = fmaxf(fmaf(acc[2][j], sc[2], sh[2]), 0.f);
        v0.w  = fmaxf(fmaf(acc[3][j], sc[3], sh[3]), 0.f);
        v1q.x = fmaxf(fmaf(acc[4][j], sc[4], sh[4]), 0.f);
        v1q.y = fmaxf(fmaf(acc[5][j], sc[5], sh[5]), 0.f);
        v1q.z = fmaxf(fmaf(acc[6][j], sc[6], sh[6]), 0.f);
        v1q.w = fmaxf(fmaf(acc[7][j], sc[7], sh[7]), 0.f);
        *(float4*)&dst[ty * 4]      = v0;
        *(float4*)&dst[64 + ty * 4] = v1q;
    }
}

// ---------------------------------------------------------------------------
// Kernel 2: brute-force 3-NN. One thread per query n2, p1 (x,y,z,|p|^2) in smem.
// score = |p1|^2 - 2*p2.p1  (|p2|^2 added back only for the weights).
// ---------------------------------------------------------------------------
__global__ __launch_bounds__(256)
void knn_kernel(const float* __restrict__ p1, const float* __restrict__ p2)
{
    extern __shared__ float4 p1s[];   // 4096 * 16B = 64 KB
    const int t  = threadIdx.x;
    const int bb = blockIdx.x >> 6;
    const int n2 = ((blockIdx.x & 63) << 8) | t;

    const float* p1b = p1 + (size_t)bb * N1V * 3;
    for (int e = t; e < N1V; e += 256) {
        float x = p1b[e * 3 + 0], y = p1b[e * 3 + 1], z = p1b[e * 3 + 2];
        p1s[e] = make_float4(x, y, z, fmaf(x, x, fmaf(y, y, z * z)));
    }
    __syncthreads();

    const float* q = p2 + ((size_t)bb * N2V + n2) * 3;
    float qx = q[0], qy = q[1], qz = q[2];
    float q2 = fmaf(qx, qx, fmaf(qy, qy, qz * qz));
    float mx = -2.f * qx, my = -2.f * qy, mz = -2.f * qz;

    float s0 = 3.4e38f, s1 = 3.4e38f, s2 = 3.4e38f;
    int   i0 = 0,       i1 = 0,       i2 = 0;

    #pragma unroll 4
    for (int j = 0; j < N1V; j++) {
        float4 f = p1s[j];
        float s = fmaf(mx, f.x, f.w);
        s = fmaf(my, f.y, s);
        s = fmaf(mz, f.z, s);
        if (s < s2) {
            if (s < s1) {
                s2 = s1; i2 = i1;
                if (s < s0) { s1 = s0; i1 = i0; s0 = s; i0 = j; }
                else        { s1 = s;  i1 = j; }
            } else { s2 = s; i2 = j; }
        }
    }

    float r0 = 1.f / (s0 + q2 + 1e-8f);
    float r1 = 1.f / (s1 + q2 + 1e-8f);
    float r2 = 1.f / (s2 + q2 + 1e-8f);
    float inv = 1.f / (r0 + r1 + r2);

    int base = (bb * N2V + n2) * 3;
    g_idx[base + 0] = i0; g_idx[base + 1] = i1; g_idx[base + 2] = i2;
    g_wgt[base + 0] = r0 * inv; g_wgt[base + 1] = r1 * inv; g_wgt[base + 2] = r2 * inv;
}

// ---------------------------------------------------------------------------
// Kernel 3: y = relu( bn( W2 @ x2 ) ) + sum_k w_k * h1T[idx_k, :]
// Same GEMM tiling; gather fused into the epilogue.
// ---------------------------------------------------------------------------
__global__ __launch_bounds__(256)
void conv2_kernel(const float* __restrict__ W2, const float* __restrict__ x2,
                  const float* __restrict__ g2, const float* __restrict__ b2,
                  const float* __restrict__ m2, const float* __restrict__ v2,
                  float* __restrict__ yout)
{
    __shared__ float As[16][136];
    __shared__ float Bs[16][128];
    __shared__ float sc_s[128], sh_s[128];
    __shared__ int   idx_s[384];
    __shared__ float w_s[384];

    const int t  = threadIdx.x;
    const int tx = t & 15, ty = t >> 4;
    const int n0  = blockIdx.x * 128;
    const int co0 = blockIdx.y * 128;
    const int bb  = blockIdx.z;

    if (t < 128) {
        int co = co0 + t;
        float sc = g2[co] * rsqrtf(v2[co] + 1e-5f);
        sc_s[t] = sc;
        sh_s[t] = b2[co] - m2[co] * sc;
    }
    {
        int base = (bb * N2V + n0) * 3;
        for (int u = t; u < 384; u += 256) {
            idx_s[u] = g_idx[base + u];
            w_s[u]   = g_wgt[base + u];
        }
    }

    const float* xb = x2 + (size_t)bb * CSKV * N2V;

    float acc[8][8];
    #pragma unroll
    for (int i = 0; i < 8; i++)
        #pragma unroll
        for (int j = 0; j < 8; j++) acc[i][j] = 0.f;

    const int arow = t & 63;
    const int akk  = (t >> 6) * 4;
    const int brow = t >> 5;
    const int bcol = (t & 31) * 4;

    for (int k0 = 0; k0 < CSKV; k0 += 16) {
        __syncthreads();
        #pragma unroll
        for (int r = 0; r < 2; r++) {
            int co_r = arow + r * 64;
            float4 w = *(const float4*)&W2[(size_t)(co0 + co_r) * CSKV + k0 + akk];
            As[akk + 0][co_r] = w.x;
            As[akk + 1][co_r] = w.y;
            As[akk + 2][co_r] = w.z;
            As[akk + 3][co_r] = w.w;
        }
        #pragma unroll
        for (int r = 0; r < 2; r++) {
            int kk = r * 8 + brow;
            *(float4*)&Bs[kk][bcol] =
                *(const float4*)&xb[(size_t)(k0 + kk) * N2V + n0 + bcol];
        }
        __syncthreads();
        #pragma unroll
        for (int kk = 0; kk < 16; kk++) {
            float4 a0 = *(const float4*)&As[kk][ty * 4];
            float4 a1 = *(const float4*)&As[kk][64 + ty * 4];
            float4 c0 = *(const float4*)&Bs[kk][tx * 4];
            float4 c1 = *(const float4*)&Bs[kk][64 + tx * 4];
            float av[8] = {a0.x, a0.y, a0.z, a0.w, a1.x, a1.y, a1.z, a1.w};
            float bv[8] = {c0.x, c0.y, c0.z, c0.w, c1.x, c1.y, c1.z, c1.w};
            #pragma unroll
            for (int i = 0; i < 8; i++)
                #pragma unroll
                for (int j = 0; j < 8; j++)
                    acc[i][j] = fmaf(av[i], bv[j], acc[i][j]);
        }
    }
    __syncthreads();

    // BN + ReLU (relu applies ONLY to the conv branch)
    float sc[8], sh[8];
    #pragma unroll
    for (int i = 0; i < 8; i++) {
        int ci = (i < 4) ? (ty * 4 + i) : (64 + ty * 4 + (i - 4));
        sc[i] = sc_s[ci];
        sh[i] = sh_s[ci];
    }
    #pragma unroll
    for (int i = 0; i < 8; i++)
        #pragma unroll
        for (int j = 0; j < 8; j++)
            acc[i][j] = fmaxf(fmaf(acc[i][j], sc[i], sh[i]), 0.f);

    // + interpolated upsample: 3-neighbor weighted gather from h1T (co-contiguous)
    #pragma unroll
    for (int j = 0; j < 8; j++) {
        int cj = (j < 4) ? (tx * 4 + j) : (64 + tx * 4 + (j - 4));
        #pragma unroll
        for (int k = 0; k < 3; k++) {
            int   id = idx_s[cj * 3 + k];
            float w  = w_s[cj * 3 + k];
            const float* src = &g_h1T[((size_t)bb * N1V + id) * COUTV + co0];
            float4 gA = *(const float4*)&src[ty * 4];
            float4 gB = *(const float4*)&src[64 + ty * 4];
            acc[0][j] = fmaf(w, gA.x, acc[0][j]);
            acc[1][j] = fmaf(w, gA.y, acc[1][j]);
            acc[2][j] = fmaf(w, gA.z, acc[2][j]);
            acc[3][j] = fmaf(w, gA.w, acc[3][j]);
            acc[4][j] = fmaf(w, gB.x, acc[4][j]);
            acc[5][j] = fmaf(w, gB.y, acc[5][j]);
            acc[6][j] = fmaf(w, gB.z, acc[6][j]);
            acc[7][j] = fmaf(w, gB.w, acc[7][j]);
        }
    }

    // store y[b][co][n2] (n-contiguous -> coalesced float4 along tx)
    #pragma unroll
    for (int i = 0; i < 8; i++) {
        int ci = (i < 4) ? (ty * 4 + i) : (64 + ty * 4 + (i - 4));
        float* drow = &yout[((size_t)(bb * COUTV + co0 + ci)) * N2V + n0];
        float4 sA = make_float4(acc[i][0], acc[i][1], acc[i][2], acc[i][3]);
        float4 sB = make_float4(acc[i][4], acc[i][5], acc[i][6], acc[i][7]);
        *(float4*)&drow[tx * 4]      = sA;
        *(float4*)&drow[64 + tx * 4] = sB;
    }
}

// ---------------------------------------------------------------------------
extern "C" void kernel_launch(void* const* d_in, const int* in_sizes, int n_in,
                              void* d_out, int out_size)
{
    const float* p1 = (const float*)d_in[0];
    const float* x1 = (const float*)d_in[1];
    const float* p2 = (const float*)d_in[2];
    const float* x2 = (const float*)d_in[3];
    const float* W1 = (const float*)d_in[4];
    const float* g1 = (const float*)d_in[5];
    const float* b1 = (const float*)d_in[6];
    const float* m1 = (const float*)d_in[7];
    const float* v1 = (const float*)d_in[8];
    const float* W2 = (const float*)d_in[9];
    const float* g2 = (const float*)d_in[10];
    const float* b2 = (const float*)d_in[11];
    const float* m2 = (const float*)d_in[12];
    const float* v2 = (const float*)d_in[13];

    float* out = (float*)d_out;
    const int P2SZ = NB * N2V * 3;
    const int YSZ  = NB * COUTV * N2V;

    float* yout = out;
    if (out_size == P2SZ + YSZ) {
        // output = (p2, y) flattened & concatenated
        cudaMemcpyAsync(out, p2, (size_t)P2SZ * sizeof(float),
                        cudaMemcpyDeviceToDevice);
        yout = out + P2SZ;
    }

    cudaFuncSetAttribute(knn_kernel,
                         cudaFuncAttributeMaxDynamicSharedMemorySize, 65536);

    conv1_kernel<<<dim3(N1V / 128, COUTV / 128, NB), 256>>>(W1, x1, g1, b1, m1, v1);
    knn_kernel<<<NB * (N2V / 256), 256, 65536>>>(p1, p2);
    conv2_kernel<<<dim3(N2V / 128, COUTV / 128, NB), 256>>>(W2, x2, g2, b2, m2, v2, yout);
}

// round 2
// speedup vs baseline: 1.1384x; 1.1384x over previous
#include <cuda_runtime.h>

#define NB    2
#define N1V   4096
#define N2V   16384
#define CINV  512
#define CSKV  256
#define COUTV 256

// Scratch (no allocations allowed): h1 transposed [b][n1][co], knn idx/weights.
__device__ float g_h1T[(size_t)NB * N1V * COUTV];
__device__ int   g_idx[NB * N2V * 3];
__device__ float g_wgt[NB * N2V * 3];

// ---------------------------------------------------------------------------
// Kernel 1: h1T[b][n][co] = relu( bn( W1 @ x1 ) )  (n-major, co contiguous)
// Tile 64(co) x 128(n) x 16(k), 256 threads, 8co x 4n microtile.
// A smem reads are warp-broadcast (ty constant within a warp).
// ---------------------------------------------------------------------------
__global__ __launch_bounds__(256, 3)
void conv1_kernel(const float* __restrict__ W1, const float* __restrict__ x1,
                  const float* __restrict__ g1, const float* __restrict__ b1,
                  const float* __restrict__ m1, const float* __restrict__ v1)
{
    __shared__ float As[16][64];    // [k][co]
    __shared__ float Bs[16][128];   // [k][n]
    __shared__ float sc_s[64], sh_s[64];

    const int t  = threadIdx.x;
    const int tx = t & 31;          // n micro: tx*4
    const int ty = t >> 5;          // co micro: ty*8
    const int n0  = blockIdx.x * 128;
    const int co0 = blockIdx.y * 64;
    const int bb  = blockIdx.z;

    if (t < 64) {
        int co = co0 + t;
        float sc = g1[co] * rsqrtf(v1[co] + 1e-5f);
        sc_s[t] = sc;
        sh_s[t] = b1[co] - m1[co] * sc;
    }

    const float* xb = x1 + (size_t)bb * CINV * N1V;

    float acc[8][4];
    #pragma unroll
    for (int i = 0; i < 8; i++)
        #pragma unroll
        for (int j = 0; j < 4; j++) acc[i][j] = 0.f;

    const int coA = t & 63;
    const int qA  = (t >> 6) * 4;   // k quad 0,4,8,12

    for (int k0 = 0; k0 < CINV; k0 += 16) {
        __syncthreads();
        {
            float4 w = *(const float4*)&W1[(size_t)(co0 + coA) * CINV + k0 + qA];
            As[qA + 0][coA] = w.x;
            As[qA + 1][coA] = w.y;
            As[qA + 2][coA] = w.z;
            As[qA + 3][coA] = w.w;
        }
        #pragma unroll
        for (int r = 0; r < 2; r++) {
            int s   = r * 256 + t;
            int row = s >> 5;
            int col = (s & 31) * 4;
            *(float4*)&Bs[row][col] =
                *(const float4*)&xb[(size_t)(k0 + row) * N1V + n0 + col];
        }
        __syncthreads();
        #pragma unroll
        for (int kk = 0; kk < 16; kk++) {
            float4 a0 = *(const float4*)&As[kk][ty * 8];
            float4 a1 = *(const float4*)&As[kk][ty * 8 + 4];
            float4 bq = *(const float4*)&Bs[kk][tx * 4];
            float av[8] = {a0.x, a0.y, a0.z, a0.w, a1.x, a1.y, a1.z, a1.w};
            float bv[4] = {bq.x, bq.y, bq.z, bq.w};
            #pragma unroll
            for (int i = 0; i < 8; i++)
                #pragma unroll
                for (int j = 0; j < 4; j++)
                    acc[i][j] = fmaf(av[i], bv[j], acc[i][j]);
        }
    }

    float sc[8], sh[8];
    #pragma unroll
    for (int i = 0; i < 8; i++) {
        sc[i] = sc_s[ty * 8 + i];
        sh[i] = sh_s[ty * 8 + i];
    }

    #pragma unroll
    for (int j = 0; j < 4; j++) {
        int n = n0 + tx * 4 + j;
        float* dst = &g_h1T[((size_t)bb * N1V + n) * COUTV + co0 + ty * 8];
        float4 v0, v1q;
        v0.x  = fmaxf(fmaf(acc[0][j], sc[0], sh[0]), 0.f);
        v0.y  = fmaxf(fmaf(acc[1][j], sc[1], sh[1]), 0.f);
        v0.z  = fmaxf(fmaf(acc[2][j], sc[2], sh[2]), 0.f);
        v0.w  = fmaxf(fmaf(acc[3][j], sc[3], sh[3]), 0.f);
        v1q.x = fmaxf(fmaf(acc[4][j], sc[4], sh[4]), 0.f);
        v1q.y = fmaxf(fmaf(acc[5][j], sc[5], sh[5]), 0.f);
        v1q.z = fmaxf(fmaf(acc[6][j], sc[6], sh[6]), 0.f);
        v1q.w = fmaxf(fmaf(acc[7][j], sc[7], sh[7]), 0.f);
        *(float4*)&dst[0] = v0;
        *(float4*)&dst[4] = v1q;
    }
}

// ---------------------------------------------------------------------------
// Kernel 2: brute-force 3-NN. One thread per query, p1 (x,y,z,|p|^2) in smem.
// 128 threads / 128 queries per block -> grid 256, better occupancy + tail.
// ---------------------------------------------------------------------------
__global__ __launch_bounds__(128)
void knn_kernel(const float* __restrict__ p1, const float* __restrict__ p2)
{
    extern __shared__ float4 p1s[];   // 4096 * 16B = 64 KB
    const int t  = threadIdx.x;
    const int bb = blockIdx.y;
    const int n2 = blockIdx.x * 128 + t;

    const float* p1b = p1 + (size_t)bb * N1V * 3;
    for (int e = t; e < N1V; e += 128) {
        float x = p1b[e * 3 + 0], y = p1b[e * 3 + 1], z = p1b[e * 3 + 2];
        p1s[e] = make_float4(x, y, z, fmaf(x, x, fmaf(y, y, z * z)));
    }
    __syncthreads();

    const float* q = p2 + ((size_t)bb * N2V + n2) * 3;
    float qx = q[0], qy = q[1], qz = q[2];
    float q2 = fmaf(qx, qx, fmaf(qy, qy, qz * qz));
    float mx = -2.f * qx, my = -2.f * qy, mz = -2.f * qz;

    float s0 = 3.4e38f, s1 = 3.4e38f, s2 = 3.4e38f;
    int   i0 = 0,       i1 = 0,       i2 = 0;

    #pragma unroll 8
    for (int j = 0; j < N1V; j++) {
        float4 f = p1s[j];
        float s = fmaf(mx, f.x, f.w);
        s = fmaf(my, f.y, s);
        s = fmaf(mz, f.z, s);
        if (s < s2) {
            if (s < s1) {
                s2 = s1; i2 = i1;
                if (s < s0) { s1 = s0; i1 = i0; s0 = s; i0 = j; }
                else        { s1 = s;  i1 = j; }
            } else { s2 = s; i2 = j; }
        }
    }

    float r0 = 1.f / (s0 + q2 + 1e-8f);
    float r1 = 1.f / (s1 + q2 + 1e-8f);
    float r2 = 1.f / (s2 + q2 + 1e-8f);
    float inv = 1.f / (r0 + r1 + r2);

    int base = (bb * N2V + n2) * 3;
    g_idx[base + 0] = i0; g_idx[base + 1] = i1; g_idx[base + 2] = i2;
    g_wgt[base + 0] = r0 * inv; g_wgt[base + 1] = r1 * inv; g_wgt[base + 2] = r2 * inv;
}

// ---------------------------------------------------------------------------
// Kernel 3: y = relu( bn( W2 @ x2 ) ) + sum_k w_k * h1T[idx_k, :]
// Same tiling as conv1; 3-NN gather fused into the epilogue (h1T co-contig).
// ---------------------------------------------------------------------------
__global__ __launch_bounds__(256, 3)
void conv2_kernel(const float* __restrict__ W2, const float* __restrict__ x2,
                  const float* __restrict__ g2, const float* __restrict__ b2,
                  const float* __restrict__ m2, const float* __restrict__ v2,
                  float* __restrict__ yout)
{
    __shared__ float As[16][64];
    __shared__ float Bs[16][128];
    __shared__ float sc_s[64], sh_s[64];
    __shared__ int   idx_s[384];
    __shared__ float w_s[384];

    const int t  = threadIdx.x;
    const int tx = t & 31;
    const int ty = t >> 5;
    const int n0  = blockIdx.x * 128;
    const int co0 = blockIdx.y * 64;
    const int bb  = blockIdx.z;

    if (t < 64) {
        int co = co0 + t;
        float sc = g2[co] * rsqrtf(v2[co] + 1e-5f);
        sc_s[t] = sc;
        sh_s[t] = b2[co] - m2[co] * sc;
    }
    {
        int base = (bb * N2V + n0) * 3;
        for (int u = t; u < 384; u += 256) {
            idx_s[u] = g_idx[base + u];
            w_s[u]   = g_wgt[base + u];
        }
    }

    const float* xb = x2 + (size_t)bb * CSKV * N2V;

    float acc[8][4];
    #pragma unroll
    for (int i = 0; i < 8; i++)
        #pragma unroll
        for (int j = 0; j < 4; j++) acc[i][j] = 0.f;

    const int coA = t & 63;
    const int qA  = (t >> 6) * 4;

    for (int k0 = 0; k0 < CSKV; k0 += 16) {
        __syncthreads();
        {
            float4 w = *(const float4*)&W2[(size_t)(co0 + coA) * CSKV + k0 + qA];
            As[qA + 0][coA] = w.x;
            As[qA + 1][coA] = w.y;
            As[qA + 2][coA] = w.z;
            As[qA + 3][coA] = w.w;
        }
        #pragma unroll
        for (int r = 0; r < 2; r++) {
            int s   = r * 256 + t;
            int row = s >> 5;
            int col = (s & 31) * 4;
            *(float4*)&Bs[row][col] =
                *(const float4*)&xb[(size_t)(k0 + row) * N2V + n0 + col];
        }
        __syncthreads();
        #pragma unroll
        for (int kk = 0; kk < 16; kk++) {
            float4 a0 = *(const float4*)&As[kk][ty * 8];
            float4 a1 = *(const float4*)&As[kk][ty * 8 + 4];
            float4 bq = *(const float4*)&Bs[kk][tx * 4];
            float av[8] = {a0.x, a0.y, a0.z, a0.w, a1.x, a1.y, a1.z, a1.w};
            float bv[4] = {bq.x, bq.y, bq.z, bq.w};
            #pragma unroll
            for (int i = 0; i < 8; i++)
                #pragma unroll
                for (int j = 0; j < 4; j++)
                    acc[i][j] = fmaf(av[i], bv[j], acc[i][j]);
        }
    }

    // BN + ReLU (conv branch only)
    float sc[8], sh[8];
    #pragma unroll
    for (int i = 0; i < 8; i++) {
        sc[i] = sc_s[ty * 8 + i];
        sh[i] = sh_s[ty * 8 + i];
    }
    #pragma unroll
    for (int i = 0; i < 8; i++)
        #pragma unroll
        for (int j = 0; j < 4; j++)
            acc[i][j] = fmaxf(fmaf(acc[i][j], sc[i], sh[i]), 0.f);

    // + interpolated upsample: 3-neighbor weighted gather from h1T
    #pragma unroll
    for (int j = 0; j < 4; j++) {
        int cj = tx * 4 + j;            // local n in [0,128)
        #pragma unroll
        for (int k = 0; k < 3; k++) {
            int   id = idx_s[cj * 3 + k];
            float w  = w_s[cj * 3 + k];
            const float* src = &g_h1T[((size_t)bb * N1V + id) * COUTV + co0 + ty * 8];
            float4 gA = *(const float4*)&src[0];
            float4 gB = *(const float4*)&src[4];
            acc[0][j] = fmaf(w, gA.x, acc[0][j]);
            acc[1][j] = fmaf(w, gA.y, acc[1][j]);
            acc[2][j] = fmaf(w, gA.z, acc[2][j]);
            acc[3][j] = fmaf(w, gA.w, acc[3][j]);
            acc[4][j] = fmaf(w, gB.x, acc[4][j]);
            acc[5][j] = fmaf(w, gB.y, acc[5][j]);
            acc[6][j] = fmaf(w, gB.z, acc[6][j]);
            acc[7][j] = fmaf(w, gB.w, acc[7][j]);
        }
    }

    // store y[b][co][n] (coalesced float4 along tx)
    #pragma unroll
    for (int i = 0; i < 8; i++) {
        int co = co0 + ty * 8 + i;
        float* drow = &yout[((size_t)(bb * COUTV + co)) * N2V + n0];
        *(float4*)&drow[tx * 4] =
            make_float4(acc[i][0], acc[i][1], acc[i][2], acc[i][3]);
    }
}

// ---------------------------------------------------------------------------
extern "C" void kernel_launch(void* const* d_in, const int* in_sizes, int n_in,
                              void* d_out, int out_size)
{
    const float* p1 = (const float*)d_in[0];
    const float* x1 = (const float*)d_in[1];
    const float* p2 = (const float*)d_in[2];
    const float* x2 = (const float*)d_in[3];
    const float* W1 = (const float*)d_in[4];
    const float* g1 = (const float*)d_in[5];
    const float* b1 = (const float*)d_in[6];
    const float* m1 = (const float*)d_in[7];
    const float* v1 = (const float*)d_in[8];
    const float* W2 = (const float*)d_in[9];
    const float* g2 = (const float*)d_in[10];
    const float* b2 = (const float*)d_in[11];
    const float* m2 = (const float*)d_in[12];
    const float* v2 = (const float*)d_in[13];

    float* out = (float*)d_out;
    const int P2SZ = NB * N2V * 3;
    const int YSZ  = NB * COUTV * N2V;

    float* yout = out;
    if (out_size == P2SZ + YSZ) {
        cudaMemcpyAsync(out, p2, (size_t)P2SZ * sizeof(float),
                        cudaMemcpyDeviceToDevice);
        yout = out + P2SZ;
    }

    cudaFuncSetAttribute(knn_kernel,
                         cudaFuncAttributeMaxDynamicSharedMemorySize, 65536);

    conv1_kernel<<<dim3(N1V / 128, COUTV / 64, NB), 256>>>(W1, x1, g1, b1, m1, v1);
    knn_kernel<<<dim3(N2V / 128, NB), 128, 65536>>>(p1, p2);
    conv2_kernel<<<dim3(N2V / 128, COUTV / 64, NB), 256>>>(W2, x2, g2, b2, m2, v2, yout);
}

// round 3
// speedup vs baseline: 1.2383x; 1.0878x over previous
#include <cuda_runtime.h>
#include <cstdint>

#define NB    2
#define N1V   4096
#define N2V   16384
#define CINV  512
#define CSKV  256
#define COUTV 256

// Scratch: h1 transposed [b][n1][co], knn idx/weights.
__device__ float g_h1T[(size_t)NB * N1V * COUTV];
__device__ int   g_idx[NB * N2V * 3];
__device__ float g_wgt[NB * N2V * 3];

// ---------------- cp.async helpers ----------------
__device__ __forceinline__ uint32_t s2u(const void* p) {
    return (uint32_t)__cvta_generic_to_shared(p);
}
__device__ __forceinline__ void cpa16(uint32_t dst, const void* src) {
    asm volatile("cp.async.cg.shared.global [%0], [%1], 16;\n" :: "r"(dst), "l"(src));
}
__device__ __forceinline__ void cpa_commit() {
    asm volatile("cp.async.commit_group;\n");
}
__device__ __forceinline__ void cpa_wait1() {
    asm volatile("cp.async.wait_group 1;\n");
}
__device__ __forceinline__ void cpa_wait0() {
    asm volatile("cp.async.wait_group 0;\n");
}

// ===========================================================================
// Fused kernel A: blocks [0,256) do conv1 (h1T = relu(bn(W1@x1))),
//                 blocks [256,384) do brute-force 3-NN.
// Both paths use the same 64KB dynamic smem region.
// conv1: tile 64co x 128n x 16k, double-buffered cp.async, 256 thr, 8co x 4n.
// ===========================================================================
__global__ __launch_bounds__(256, 3)
void front_kernel(const float* __restrict__ W1, const float* __restrict__ x1,
                  const float* __restrict__ g1, const float* __restrict__ b1,
                  const float* __restrict__ m1, const float* __restrict__ v1,
                  const float* __restrict__ p1, const float* __restrict__ p2)
{
    extern __shared__ char SRAW[];
    const int t   = threadIdx.x;
    const int bid = blockIdx.x;

    if (bid < 256) {
        // ------------------------- conv1 path -------------------------
        // smem: As[2][64][16] @0 (8KB), Bs[2][16][128] @8KB (16KB), sc/sh @24KB
        float* AsB  = (float*)SRAW;              // buf*1024 + co*16 + kk
        float* BsB  = (float*)(SRAW + 8192);     // buf*2048 + kk*128 + n
        float* sc_s = (float*)(SRAW + 24576);
        float* sh_s = sc_s + 64;

        const int tx = t & 31;          // n micro: tx*4
        const int ty = t >> 5;          // co micro: ty*8
        const int n0  = (bid & 31) * 128;
        const int co0 = ((bid >> 5) & 3) * 64;
        const int bb  = bid >> 7;

        if (t < 64) {
            int co = co0 + t;
            float sc = g1[co] * rsqrtf(v1[co] + 1e-5f);
            sc_s[t] = sc;
            sh_s[t] = b1[co] - m1[co] * sc;
        }

        const float* xb = x1 + (size_t)bb * CINV * N1V;

        // cp.async roles
        const int a_co   = t >> 2;            // 0..63
        const int a_q    = (t & 3) * 4;       // k quad
        const uint32_t sA = s2u(AsB) + (uint32_t)(a_co * 16 + a_q) * 4u;
        const int b_row0 = t >> 5;            // chunk c = t      : row 0..7
        const int b_col0 = (t & 31) * 4;
        const int b_row1 = 8 + (t >> 5);      // chunk c = t+256
        const uint32_t sB0 = s2u(BsB) + (uint32_t)(b_row0 * 128 + b_col0) * 4u;
        const uint32_t sB1 = s2u(BsB) + (uint32_t)(b_row1 * 128 + b_col0) * 4u;

        float acc[8][4];
        #pragma unroll
        for (int i = 0; i < 8; i++)
            #pragma unroll
            for (int j = 0; j < 4; j++) acc[i][j] = 0.f;

        const int NCH = CINV / 16;      // 32

        // prologue: prefetch chunk 0 into buf 0
        cpa16(sA, &W1[(size_t)(co0 + a_co) * CINV + a_q]);
        cpa16(sB0, &xb[(size_t)b_row0 * N1V + n0 + b_col0]);
        cpa16(sB1, &xb[(size_t)b_row1 * N1V + n0 + b_col0]);
        cpa_commit();

        for (int ch = 0; ch < NCH; ch++) {
            const int cur = ch & 1;
            if (ch + 1 < NCH) {
                const int nxt = cur ^ 1;
                const int k0  = (ch + 1) * 16;
                cpa16(sA + nxt * 4096u, &W1[(size_t)(co0 + a_co) * CINV + k0 + a_q]);
                cpa16(sB0 + nxt * 8192u, &xb[(size_t)(k0 + b_row0) * N1V + n0 + b_col0]);
                cpa16(sB1 + nxt * 8192u, &xb[(size_t)(k0 + b_row1) * N1V + n0 + b_col0]);
                cpa_commit();
                cpa_wait1();
            } else {
                cpa_wait0();
            }
            __syncthreads();

            const float* Ab = AsB + cur * 1024 + (ty * 8) * 16;
            const float* Bb = BsB + cur * 2048;
            #pragma unroll
            for (int kk = 0; kk < 16; kk++) {
                float4 bq = *(const float4*)&Bb[kk * 128 + tx * 4];
                float bv[4] = {bq.x, bq.y, bq.z, bq.w};
                #pragma unroll
                for (int i = 0; i < 8; i++) {
                    float a = Ab[i * 16 + kk];   // warp-uniform (broadcast)
                    acc[i][0] = fmaf(a, bv[0], acc[i][0]);
                    acc[i][1] = fmaf(a, bv[1], acc[i][1]);
                    acc[i][2] = fmaf(a, bv[2], acc[i][2]);
                    acc[i][3] = fmaf(a, bv[3], acc[i][3]);
                }
            }
            __syncthreads();
        }

        float sc[8], sh[8];
        #pragma unroll
        for (int i = 0; i < 8; i++) {
            sc[i] = sc_s[ty * 8 + i];
            sh[i] = sh_s[ty * 8 + i];
        }
        #pragma unroll
        for (int j = 0; j < 4; j++) {
            int n = n0 + tx * 4 + j;
            float* dst = &g_h1T[((size_t)bb * N1V + n) * COUTV + co0 + ty * 8];
            float4 v0, v1q;
            v0.x  = fmaxf(fmaf(acc[0][j], sc[0], sh[0]), 0.f);
            v0.y  = fmaxf(fmaf(acc[1][j], sc[1], sh[1]), 0.f);
            v0.z  = fmaxf(fmaf(acc[2][j], sc[2], sh[2]), 0.f);
            v0.w  = fmaxf(fmaf(acc[3][j], sc[3], sh[3]), 0.f);
            v1q.x = fmaxf(fmaf(acc[4][j], sc[4], sh[4]), 0.f);
            v1q.y = fmaxf(fmaf(acc[5][j], sc[5], sh[5]), 0.f);
            v1q.z = fmaxf(fmaf(acc[6][j], sc[6], sh[6]), 0.f);
            v1q.w = fmaxf(fmaf(acc[7][j], sc[7], sh[7]), 0.f);
            *(float4*)&dst[0] = v0;
            *(float4*)&dst[4] = v1q;
        }
    } else {
        // ------------------------- knn path -------------------------
        float4* p1s = (float4*)SRAW;    // 4096 * 16B = 64KB
        const int kbid = bid - 256;
        const int bb   = kbid >> 6;
        const int n2   = ((kbid & 63) << 8) | t;

        const float* p1b = p1 + (size_t)bb * N1V * 3;
        for (int e = t; e < N1V; e += 256) {
            float x = p1b[e * 3 + 0], y = p1b[e * 3 + 1], z = p1b[e * 3 + 2];
            p1s[e] = make_float4(x, y, z, fmaf(x, x, fmaf(y, y, z * z)));
        }
        __syncthreads();

        const float* q = p2 + ((size_t)bb * N2V + n2) * 3;
        float qx = q[0], qy = q[1], qz = q[2];
        float q2 = fmaf(qx, qx, fmaf(qy, qy, qz * qz));
        float mx = -2.f * qx, my = -2.f * qy, mz = -2.f * qz;

        float s0 = 3.4e38f, s1 = 3.4e38f, s2 = 3.4e38f;
        int   i0 = 0,       i1 = 0,       i2 = 0;

        #pragma unroll 4
        for (int j = 0; j < N1V; j++) {
            float4 f = p1s[j];
            float s = fmaf(mx, f.x, f.w);
            s = fmaf(my, f.y, s);
            s = fmaf(mz, f.z, s);
            if (s < s2) {
                if (s < s1) {
                    s2 = s1; i2 = i1;
                    if (s < s0) { s1 = s0; i1 = i0; s0 = s; i0 = j; }
                    else        { s1 = s;  i1 = j; }
                } else { s2 = s; i2 = j; }
            }
        }

        float r0 = 1.f / (s0 + q2 + 1e-8f);
        float r1 = 1.f / (s1 + q2 + 1e-8f);
        float r2 = 1.f / (s2 + q2 + 1e-8f);
        float inv = 1.f / (r0 + r1 + r2);

        int base = (bb * N2V + n2) * 3;
        g_idx[base + 0] = i0; g_idx[base + 1] = i1; g_idx[base + 2] = i2;
        g_wgt[base + 0] = r0 * inv; g_wgt[base + 1] = r1 * inv; g_wgt[base + 2] = r2 * inv;
    }
}

// ===========================================================================
// Kernel B: y = relu(bn(W2@x2)) + 3-NN weighted gather of h1T.
// Same pipelined GEMM, gather fused in the epilogue.
// ===========================================================================
__global__ __launch_bounds__(256, 3)
void conv2_kernel(const float* __restrict__ W2, const float* __restrict__ x2,
                  const float* __restrict__ g2, const float* __restrict__ b2,
                  const float* __restrict__ m2, const float* __restrict__ v2,
                  float* __restrict__ yout)
{
    __shared__ float AsB[2 * 64 * 16];     // buf*1024 + co*16 + kk
    __shared__ float BsB[2 * 16 * 128];    // buf*2048 + kk*128 + n
    __shared__ float sc_s[64], sh_s[64];
    __shared__ int   idx_s[384];
    __shared__ float w_s[384];

    const int t  = threadIdx.x;
    const int tx = t & 31;
    const int ty = t >> 5;
    const int n0  = blockIdx.x * 128;
    const int co0 = blockIdx.y * 64;
    const int bb  = blockIdx.z;

    if (t < 64) {
        int co = co0 + t;
        float sc = g2[co] * rsqrtf(v2[co] + 1e-5f);
        sc_s[t] = sc;
        sh_s[t] = b2[co] - m2[co] * sc;
    }
    {
        int base = (bb * N2V + n0) * 3;
        for (int u = t; u < 384; u += 256) {
            idx_s[u] = g_idx[base + u];
            w_s[u]   = g_wgt[base + u];
        }
    }

    const float* xb = x2 + (size_t)bb * CSKV * N2V;

    const int a_co   = t >> 2;
    const int a_q    = (t & 3) * 4;
    const uint32_t sA = s2u(AsB) + (uint32_t)(a_co * 16 + a_q) * 4u;
    const int b_row0 = t >> 5;
    const int b_col0 = (t & 31) * 4;
    const int b_row1 = 8 + (t >> 5);
    const uint32_t sB0 = s2u(BsB) + (uint32_t)(b_row0 * 128 + b_col0) * 4u;
    const uint32_t sB1 = s2u(BsB) + (uint32_t)(b_row1 * 128 + b_col0) * 4u;

    float acc[8][4];
    #pragma unroll
    for (int i = 0; i < 8; i++)
        #pragma unroll
        for (int j = 0; j < 4; j++) acc[i][j] = 0.f;

    const int NCH = CSKV / 16;   // 16

    cpa16(sA, &W2[(size_t)(co0 + a_co) * CSKV + a_q]);
    cpa16(sB0, &xb[(size_t)b_row0 * N2V + n0 + b_col0]);
    cpa16(sB1, &xb[(size_t)b_row1 * N2V + n0 + b_col0]);
    cpa_commit();

    for (int ch = 0; ch < NCH; ch++) {
        const int cur = ch & 1;
        if (ch + 1 < NCH) {
            const int nxt = cur ^ 1;
            const int k0  = (ch + 1) * 16;
            cpa16(sA + nxt * 4096u, &W2[(size_t)(co0 + a_co) * CSKV + k0 + a_q]);
            cpa16(sB0 + nxt * 8192u, &xb[(size_t)(k0 + b_row0) * N2V + n0 + b_col0]);
            cpa16(sB1 + nxt * 8192u, &xb[(size_t)(k0 + b_row1) * N2V + n0 + b_col0]);
            cpa_commit();
            cpa_wait1();
        } else {
            cpa_wait0();
        }
        __syncthreads();

        const float* Ab = AsB + cur * 1024 + (ty * 8) * 16;
        const float* Bb = BsB + cur * 2048;
        #pragma unroll
        for (int kk = 0; kk < 16; kk++) {
            float4 bq = *(const float4*)&Bb[kk * 128 + tx * 4];
            float bv[4] = {bq.x, bq.y, bq.z, bq.w};
            #pragma unroll
            for (int i = 0; i < 8; i++) {
                float a = Ab[i * 16 + kk];   // warp-uniform
                acc[i][0] = fmaf(a, bv[0], acc[i][0]);
                acc[i][1] = fmaf(a, bv[1], acc[i][1]);
                acc[i][2] = fmaf(a, bv[2], acc[i][2]);
                acc[i][3] = fmaf(a, bv[3], acc[i][3]);
            }
        }
        __syncthreads();
    }

    // BN + ReLU (conv branch only)
    float sc[8], sh[8];
    #pragma unroll
    for (int i = 0; i < 8; i++) {
        sc[i] = sc_s[ty * 8 + i];
        sh[i] = sh_s[ty * 8 + i];
    }
    #pragma unroll
    for (int i = 0; i < 8; i++)
        #pragma unroll
        for (int j = 0; j < 4; j++)
            acc[i][j] = fmaxf(fmaf(acc[i][j], sc[i], sh[i]), 0.f);

    // + interpolated upsample: 3-neighbor weighted gather from h1T (co-contig)
    #pragma unroll
    for (int j = 0; j < 4; j++) {
        int cj = tx * 4 + j;
        #pragma unroll
        for (int k = 0; k < 3; k++) {
            int   id = idx_s[cj * 3 + k];
            float w  = w_s[cj * 3 + k];
            const float* src = &g_h1T[((size_t)bb * N1V + id) * COUTV + co0 + ty * 8];
            float4 gA = *(const float4*)&src[0];
            float4 gB = *(const float4*)&src[4];
            acc[0][j] = fmaf(w, gA.x, acc[0][j]);
            acc[1][j] = fmaf(w, gA.y, acc[1][j]);
            acc[2][j] = fmaf(w, gA.z, acc[2][j]);
            acc[3][j] = fmaf(w, gA.w, acc[3][j]);
            acc[4][j] = fmaf(w, gB.x, acc[4][j]);
            acc[5][j] = fmaf(w, gB.y, acc[5][j]);
            acc[6][j] = fmaf(w, gB.z, acc[6][j]);
            acc[7][j] = fmaf(w, gB.w, acc[7][j]);
        }
    }

    // store y[b][co][n] (coalesced float4 along tx)
    #pragma unroll
    for (int i = 0; i < 8; i++) {
        int co = co0 + ty * 8 + i;
        float* drow = &yout[((size_t)(bb * COUTV + co)) * N2V + n0];
        *(float4*)&drow[tx * 4] =
            make_float4(acc[i][0], acc[i][1], acc[i][2], acc[i][3]);
    }
}

// ---------------------------------------------------------------------------
extern "C" void kernel_launch(void* const* d_in, const int* in_sizes, int n_in,
                              void* d_out, int out_size)
{
    const float* p1 = (const float*)d_in[0];
    const float* x1 = (const float*)d_in[1];
    const float* p2 = (const float*)d_in[2];
    const float* x2 = (const float*)d_in[3];
    const float* W1 = (const float*)d_in[4];
    const float* g1 = (const float*)d_in[5];
    const float* b1 = (const float*)d_in[6];
    const float* m1 = (const float*)d_in[7];
    const float* v1 = (const float*)d_in[8];
    const float* W2 = (const float*)d_in[9];
    const float* g2 = (const float*)d_in[10];
    const float* b2 = (const float*)d_in[11];
    const float* m2 = (const float*)d_in[12];
    const float* v2 = (const float*)d_in[13];

    float* out = (float*)d_out;
    const int P2SZ = NB * N2V * 3;
    const int YSZ  = NB * COUTV * N2V;

    float* yout = out;
    if (out_size == P2SZ + YSZ) {
        cudaMemcpyAsync(out, p2, (size_t)P2SZ * sizeof(float),
                        cudaMemcpyDeviceToDevice);
        yout = out + P2SZ;
    }

    cudaFuncSetAttribute(front_kernel,
                         cudaFuncAttributeMaxDynamicSharedMemorySize, 65536);

    // 256 conv1 blocks + 128 knn blocks, co-resident (overlapped)
    front_kernel<<<384, 256, 65536>>>(W1, x1, g1, b1, m1, v1, p1, p2);
    conv2_kernel<<<dim3(N2V / 128, COUTV / 64, NB), 256>>>(W2, x2, g2, b2, m2, v2, yout);
}